// round 15
// baseline (speedup 1.0000x reference)
#include <cuda_runtime.h>
#include <cuda_fp16.h>
#include <math.h>
#include <stdint.h>

// ---------------------------------------------------------------------------
// Problem constants
// ---------------------------------------------------------------------------
constexpr int B     = 4;
constexpr int S     = 2048;
constexpr int EMBED = 2048;
constexpr int DC    = 512;     // D_COMPR
constexpr int DR    = 128;     // D_ROPE
constexpr int DCC   = DC - DR; // 384
constexpr int H     = 8;
constexpr int HD    = 64;      // head dim
constexpr int M     = B * S;   // 8192 rows

// weight offsets (elements) inside g_wh (single fp16 plane)
constexpr size_t OFF_Q   = 0;
constexpr size_t OFF_KV  = OFF_Q   + 512 * 2048;
constexpr size_t OFF_QR  = OFF_KV  + 512 * 2048;
constexpr size_t OFF_KR  = OFF_QR  + 128 * 2048;
constexpr size_t OFF_QC  = OFF_KR  + 128 * 2048;
constexpr size_t OFF_KC  = OFF_QC  + 384 * 512;
constexpr size_t OFF_V   = OFF_KC  + 384 * 512;
constexpr size_t OFF_OUT = OFF_V   + 512 * 512;
constexpr size_t W_TOTAL = OFF_OUT + 2048 * 512;

// ---------------------------------------------------------------------------
// Scratch (device globals; allocation is forbidden)
// ---------------------------------------------------------------------------
__device__ __align__(16) __half g_x [(size_t)M * 2048];
__device__ __align__(16) __half g_wh[W_TOTAL];
__device__ __align__(16) __half g_cqkv[(size_t)M * 1024];
__device__ __align__(16) __half g_q [(size_t)M * 512];
__device__ __align__(16) __half g_k [(size_t)M * 512];
__device__ __align__(16) __half g_v [(size_t)M * 512];
__device__ __align__(16) __half g_o [(size_t)M * 512];
__device__ float g_qr [M * 256];       // cols 0-127: cqr, 128-255: ckr (pre-rope)

__device__ __forceinline__ float gelu_exact(float v) {
    return 0.5f * v * (1.0f + erff(v * 0.70710678118654752f));
}

// fp32 pair -> f16x2
__device__ __forceinline__ uint32_t pack_f16(float e0, float e1) {
    uint32_t h;
    asm("cvt.rn.f16x2.f32 %0, %1, %2;" : "=r"(h) : "f"(e1), "f"(e0));
    return h;
}

// FMA-pipe exp (no MUFU): exp(x) for x <= 0, clamped at -80.
__device__ __forceinline__ float fast_exp(float x) {
    x = fmaxf(x, -80.0f);
    float t = fmaf(x, 1.4426950408889634f, 12582912.0f);
    float i = t - 12582912.0f;
    float f = fmaf(x, 1.4426950408889634f, -i);
    float p = 1.3333558146e-3f;
    p = fmaf(p, f, 9.6181291076e-3f);
    p = fmaf(p, f, 5.5504108665e-2f);
    p = fmaf(p, f, 2.4022650696e-1f);
    p = fmaf(p, f, 6.9314718056e-1f);
    p = fmaf(p, f, 1.0f);
    return __int_as_float(__float_as_int(p) +
                          ((__float_as_int(t) - 0x4B400000) << 23));
}

__device__ __forceinline__ uint32_t smem_u32(const void* p) {
    uint32_t a;
    asm("{ .reg .u64 t; cvta.to.shared.u64 t, %1; cvt.u32.u64 %0, t; }"
        : "=r"(a) : "l"(p));
    return a;
}

#define CP16(dst, src) \
    asm volatile("cp.async.cg.shared.global [%0], [%1], 16;" \
                 :: "r"(dst), "l"(src) : "memory")
#define CP_COMMIT() asm volatile("cp.async.commit_group;" ::: "memory")
#define CP_WAIT0()  asm volatile("cp.async.wait_group 0;" ::: "memory")
#define CP_WAIT1()  asm volatile("cp.async.wait_group 1;" ::: "memory")

#define LDSM4(r0, r1, r2, r3, addr) \
    asm volatile("ldmatrix.sync.aligned.m8n8.x4.shared.b16 {%0,%1,%2,%3}, [%4];" \
                 : "=r"(r0), "=r"(r1), "=r"(r2), "=r"(r3) : "r"(addr))
#define LDSM4T(r0, r1, r2, r3, addr) \
    asm volatile("ldmatrix.sync.aligned.m8n8.x4.trans.shared.b16 {%0,%1,%2,%3}, [%4];" \
                 : "=r"(r0), "=r"(r1), "=r"(r2), "=r"(r3) : "r"(addr))

#define MMA_F16(d, a, b) \
    asm volatile("mma.sync.aligned.m16n8k16.row.col.f32.f16.f16.f32 " \
                 "{%0,%1,%2,%3},{%4,%5,%6,%7},{%8,%9},{%0,%1,%2,%3};" \
                 : "+f"((d)[0]), "+f"((d)[1]), "+f"((d)[2]), "+f"((d)[3]) \
                 : "r"((a)[0]), "r"((a)[1]), "r"((a)[2]), "r"((a)[3]), \
                   "r"((b)[0]), "r"((b)[1]))

// ---------------------------------------------------------------------------
// fp32 -> fp16 (x)
// ---------------------------------------------------------------------------
__global__ void cvt_x(const float* __restrict__ src,
                      __half* __restrict__ dst, int n4) {
    int i = blockIdx.x * blockDim.x + threadIdx.x;
    if (i >= n4) return;
    float4 v = ((const float4*)src)[i];
    ((uint2*)dst)[i] = make_uint2(pack_f16(v.x, v.y), pack_f16(v.z, v.w));
}

// ---------------------------------------------------------------------------
// All 8 weights -> g_wh (single fp16 plane) in one launch
// ---------------------------------------------------------------------------
constexpr size_t QB0 = OFF_KV  / 4;
constexpr size_t QB1 = OFF_QR  / 4;
constexpr size_t QB2 = OFF_KR  / 4;
constexpr size_t QB3 = OFF_QC  / 4;
constexpr size_t QB4 = OFF_KC  / 4;
constexpr size_t QB5 = OFF_V   / 4;
constexpr size_t QB6 = OFF_OUT / 4;
constexpr size_t QB7 = W_TOTAL / 4;

__global__ void cvt_weights(const float* __restrict__ s0, const float* __restrict__ s1,
                            const float* __restrict__ s2, const float* __restrict__ s3,
                            const float* __restrict__ s4, const float* __restrict__ s5,
                            const float* __restrict__ s6, const float* __restrict__ s7,
                            __half* __restrict__ wh) {
    size_t i = (size_t)blockIdx.x * blockDim.x + threadIdx.x;
    if (i >= QB7) return;
    const float* src; size_t base;
    if      (i < QB0) { src = s0; base = 0;   }
    else if (i < QB1) { src = s1; base = QB0; }
    else if (i < QB2) { src = s2; base = QB1; }
    else if (i < QB3) { src = s3; base = QB2; }
    else if (i < QB4) { src = s4; base = QB3; }
    else if (i < QB5) { src = s5; base = QB4; }
    else if (i < QB6) { src = s6; base = QB5; }
    else              { src = s7; base = QB6; }
    float4 v = ((const float4*)src)[i - base];
    ((uint2*)wh)[i] = make_uint2(pack_f16(v.x, v.y), pack_f16(v.z, v.w));
}

// ---------------------------------------------------------------------------
// Fused multi-tile GEMM via mma.sync (single fp16, fp32 accumulate)
// 256x128 CTA tile, 512 threads (16 warps, 4m x 4n, 64x32 warp tile),
// BK=32, 3-stage cp.async pipeline (90 KB smem -> 2 CTAs/SM),
// ONE __syncthreads per kt.
// mode bits: 1 = GELU, 2 = write fp32 C, 4 = write fp16 plane (Ch).
// ---------------------------------------------------------------------------
struct TileP {
    const __half *Ah, *Wh;
    const float* bias;
    float* Cf;
    void *Ch;
    int lda, ldc, ldh, mode;
    float scale;
};
struct TileArr16 { TileP t[16]; };

constexpr int SM_AH = 0;          // 256 rows * 80B = 20480
constexpr int SM_BH = 20480;      // 128 rows * 80B = 10240
constexpr int SM_STAGE = 30720;
constexpr int GEMM_SMEM = 3 * SM_STAGE;   // 92160 -> 2 CTAs/SM

__global__ void __launch_bounds__(512)
gemm_tiles(TileArr16 ta, int K) {
    const TileP tp = ta.t[blockIdx.x];

    extern __shared__ char smem[];
    const uint32_t sb = smem_u32(smem);

    const int tid    = threadIdx.x;
    const int lane   = tid & 31;
    const int wid    = tid >> 5;
    const int warp_m = wid >> 2;        // 0..3
    const int warp_n = wid & 3;         // 0..3
    const int bm     = blockIdx.y * 256;

    // staging: A (2 threads/row, 32B each), B (4 threads/row, 16B each)
    const int arow = tid >> 1;                       // 0..255
    const int acb  = (tid & 1) * 32;                 // byte chunk in 64B row
    const __half* gA = tp.Ah + (size_t)(bm + arow) * tp.lda + acb / 2;
    const uint32_t sA = (uint32_t)(arow * 80 + acb);

    const int brow = tid >> 2;                       // 0..127
    const int bcb  = (tid & 3) * 16;
    const __half* gB = tp.Wh + (size_t)brow * K + bcb / 2;
    const uint32_t sB = (uint32_t)(brow * 80 + bcb);

    const uint32_t aBase = (uint32_t)((warp_m * 64 + (lane & 15)) * 80 +
                                      ((lane >> 4) << 4));
    const uint32_t bBase = (uint32_t)((warp_n * 32 + (lane & 7) +
                                       ((lane & 16) >> 1)) * 80 +
                                      (((lane >> 3) & 1) << 4));

    float d[4][4][4];
    #pragma unroll
    for (int i = 0; i < 4; ++i)
        #pragma unroll
        for (int j = 0; j < 4; ++j)
            #pragma unroll
            for (int k = 0; k < 4; ++k) d[i][j][k] = 0.0f;

    auto load_stage = [&](int s, int kt) {
        const uint32_t sbase = sb + s * SM_STAGE;
        const int ge = kt * 32;        // element offset
        CP16(sbase + SM_AH + sA,      gA + ge);
        CP16(sbase + SM_AH + sA + 16, gA + ge + 8);
        CP16(sbase + SM_BH + sB,      gB + ge);
    };

    const int KT = K >> 5;   // >= 16 always
    load_stage(0, 0); CP_COMMIT();
    load_stage(1, 1); CP_COMMIT();

    int slot = 0;
    for (int kt = 0; kt < KT; ++kt) {
        CP_WAIT1();          // stage kt landed (<=1 group outstanding)
        __syncthreads();     // all warps done with stage kt-1 (overwrite target)

        if (kt + 2 < KT) {
            int s2 = slot + 2; if (s2 >= 3) s2 -= 3;
            load_stage(s2, kt + 2);
        }
        CP_COMMIT();

        const uint32_t stage = sb + slot * SM_STAGE;
        #pragma unroll
        for (int k16 = 0; k16 < 2; ++k16) {
            uint32_t bh[4][2];
            #pragma unroll
            for (int np = 0; np < 2; ++np) {
                uint32_t addr = stage + bBase + np * (16 * 80) + k16 * 32;
                LDSM4(bh[2*np][0], bh[2*np][1], bh[2*np+1][0], bh[2*np+1][1],
                      addr + SM_BH);
            }
            #pragma unroll
            for (int mt = 0; mt < 4; ++mt) {
                uint32_t ah[4];
                uint32_t addr = stage + aBase + mt * (16 * 80) + k16 * 32;
                LDSM4(ah[0], ah[1], ah[2], ah[3], addr + SM_AH);
                #pragma unroll
                for (int nt = 0; nt < 4; ++nt)
                    MMA_F16(d[mt][nt], ah, bh[nt]);
            }
        }
        if (++slot == 3) slot = 0;
    }

    // ------------------------- epilogue -------------------------
    const int grp  = lane >> 2;
    const int qd   = lane & 3;
    const int mode = tp.mode;
    const float sc = tp.scale;
    #pragma unroll
    for (int mt = 0; mt < 4; ++mt) {
        const int r0 = bm + warp_m * 64 + mt * 16 + grp;
        const int r1 = r0 + 8;
        #pragma unroll
        for (int nt = 0; nt < 4; ++nt) {
            const int col = warp_n * 32 + nt * 8 + qd * 2;
            float2 bb = *(const float2*)&tp.bias[col];
            float v00 = d[mt][nt][0] + bb.x;
            float v01 = d[mt][nt][1] + bb.y;
            float v10 = d[mt][nt][2] + bb.x;
            float v11 = d[mt][nt][3] + bb.y;
            if (mode & 1) {
                v00 = gelu_exact(v00); v01 = gelu_exact(v01);
                v10 = gelu_exact(v10); v11 = gelu_exact(v11);
            }
            v00 *= sc; v01 *= sc; v10 *= sc; v11 *= sc;
            if (mode & 2) {
                *(float2*)&tp.Cf[(size_t)r0 * tp.ldc + col] = make_float2(v00, v01);
                *(float2*)&tp.Cf[(size_t)r1 * tp.ldc + col] = make_float2(v10, v11);
            }
            if (mode & 4) {
                __half* Chp = (__half*)tp.Ch;
                *(uint32_t*)&Chp[(size_t)r0 * tp.ldh + col] = pack_f16(v00, v01);
                *(uint32_t*)&Chp[(size_t)r1 * tp.ldh + col] = pack_f16(v10, v11);
            }
        }
    }
}

// ---------------------------------------------------------------------------
// Rope-only builder for Q/K columns [384, 512). Q/K single fp16.
// ---------------------------------------------------------------------------
__global__ void rope_planes(const float* __restrict__ qr,
                            __half* __restrict__ qp, __half* __restrict__ kp) {
    int idx = blockIdx.x * blockDim.x + threadIdx.x;   // M*64
    if (idx >= M * 64) return;
    int m  = idx >> 6;
    int jp = (idx & 63) * 2;
    int s  = m & (S - 1);

    float vq[2], vk[2];
    #pragma unroll
    for (int e = 0; e < 2; ++e) {
        int jj = jp + e;
        int i  = jj & 63;
        float invf = expf(-(float)i * (9.2103403719761836f / 64.0f));
        float ang  = (float)s * invf;
        float sv, cv; sincosf(ang, &sv, &cv);
        float xq = qr[m * 256 + jj];
        float xk = qr[m * 256 + 128 + jj];
        float rq, rk;
        if (jj < 64) { rq = -qr[m * 256 + jj + 64]; rk = -qr[m * 256 + 128 + jj + 64]; }
        else         { rq =  qr[m * 256 + jj - 64]; rk =  qr[m * 256 + 128 + jj - 64]; }
        vq[e] = gelu_exact(xq * cv + rq * sv) * 0.125f;
        vk[e] = gelu_exact(xk * cv + rk * sv);
    }
    size_t o = (size_t)m * DC + DCC + jp;
    *(uint32_t*)&qp[o] = pack_f16(vq[0], vq[1]);
    *(uint32_t*)&kp[o] = pack_f16(vk[0], vk[1]);
}

// ---------------------------------------------------------------------------
// Flash attention via mma.sync, single fp16 Q/K/P/V, fp32 accum/softmax.
// 2-stage KV pipeline, 55.3 KB smem. qt reversed for load balance.
// ---------------------------------------------------------------------------
constexpr int AT_Q    = 0;                 // 128 rows * 144B = 18432
constexpr int AT_ST0  = 18432;
constexpr int AT_K    = 0;                 // within stage: 64 rows * 144B = 9216
constexpr int AT_V    = 9216;
constexpr int AT_STSZ = 18432;
constexpr int ATTN_SMEM = AT_ST0 + 2 * AT_STSZ;   // 55296

__global__ void __launch_bounds__(256)
attn_mma(const __half* __restrict__ Qp, const __half* __restrict__ Kp,
         const __half* __restrict__ Vp, __half* __restrict__ O) {
    extern __shared__ char smem[];
    const uint32_t sb = smem_u32(smem);

    const int qt = gridDim.x - 1 - blockIdx.x;   // heavy tiles first
    const int h = blockIdx.y, b = blockIdx.z;
    const int q0 = qt * 128;
    const int tid  = threadIdx.x;
    const int lane = tid & 31;
    const int wid  = tid >> 5;
    const int m0   = wid * 16;
    const int grp  = lane >> 2;
    const int qd   = lane & 3;
    const int bS   = b * S;
    const size_t hoff = (size_t)h * HD;

    auto load_kv = [&](int kt, int buf) {
        const uint32_t stage = sb + AT_ST0 + buf * AT_STSZ;
        int r  = tid >> 2;
        int ch = (tid & 3) * 2;
        size_t g = (size_t)(bS + kt * 64 + r) * DC + hoff + ch * 8;
        uint32_t sdst = stage + r * 144 + ch * 16;
        #pragma unroll
        for (int c = 0; c < 2; ++c) {
            CP16(sdst + AT_K + c * 16, Kp + g + c * 8);
            CP16(sdst + AT_V + c * 16, Vp + g + c * 8);
        }
    };

    {
        int r  = tid >> 1;
        int ch = (tid & 1) * 4;
        size_t g = (size_t)(bS + q0 + r) * DC + hoff + ch * 8;
        uint32_t sdst = sb + AT_Q + r * 144 + ch * 16;
        #pragma unroll
        for (int c = 0; c < 4; ++c)
            CP16(sdst + c * 16, Qp + g + c * 8);
    }
    load_kv(0, 0);
    CP_COMMIT();

    float mrow[2] = {-1e30f, -1e30f};
    float lrow[2] = {0.0f, 0.0f};
    float acc[8][4];
    #pragma unroll
    for (int j = 0; j < 8; ++j)
        #pragma unroll
        for (int c = 0; c < 4; ++c) acc[j][c] = 0.0f;

    const uint32_t aBase = sb + AT_Q + (m0 + (lane & 15)) * 144 +
                           ((lane >> 4) << 4);
    const uint32_t bRow  = ((lane & 7) + ((lane & 16) >> 1)) * 144 +
                           (((lane >> 3) & 1) << 4);
    const uint32_t vRow  = (lane & 15) * 144 + ((lane >> 4) << 4);

    const int kt_end = 2 * qt + 1;
    for (int kt = 0; kt <= kt_end; ++kt) {
        CP_WAIT0();
        __syncthreads();
        if (kt < kt_end) { load_kv(kt + 1, (kt + 1) & 1); }
        CP_COMMIT();

        const uint32_t stage = sb + AT_ST0 + (kt & 1) * AT_STSZ;
        const int k0 = kt * 64;

        float s[8][4];
        #pragma unroll
        for (int j = 0; j < 8; ++j)
            #pragma unroll
            for (int c = 0; c < 4; ++c) s[j][c] = 0.0f;

        #pragma unroll
        for (int k16 = 0; k16 < 4; ++k16) {
            uint32_t qh[4];
            LDSM4(qh[0], qh[1], qh[2], qh[3], aBase + k16 * 32);
            #pragma unroll
            for (int np = 0; np < 4; ++np) {
                uint32_t kk[4];
                uint32_t baddr = stage + bRow + np * (16 * 144) + k16 * 32;
                LDSM4(kk[0], kk[1], kk[2], kk[3], baddr + AT_K);
                MMA_F16(s[2*np],   qh, kk);
                MMA_F16(s[2*np+1], qh, kk + 2);
            }
        }

        const int row0 = q0 + m0 + grp;
        if (k0 + 63 > q0 + m0) {
            #pragma unroll
            for (int j = 0; j < 8; ++j) {
                int kg = k0 + j * 8 + qd * 2;
                if (kg     > row0)     s[j][0] = -1e30f;
                if (kg + 1 > row0)     s[j][1] = -1e30f;
                if (kg     > row0 + 8) s[j][2] = -1e30f;
                if (kg + 1 > row0 + 8) s[j][3] = -1e30f;
            }
        }

        float mx0 = -1e30f, mx1 = -1e30f;
        #pragma unroll
        for (int j = 0; j < 8; ++j) {
            mx0 = fmaxf(mx0, fmaxf(s[j][0], s[j][1]));
            mx1 = fmaxf(mx1, fmaxf(s[j][2], s[j][3]));
        }
        mx0 = fmaxf(mx0, __shfl_xor_sync(0xFFFFFFFF, mx0, 1));
        mx0 = fmaxf(mx0, __shfl_xor_sync(0xFFFFFFFF, mx0, 2));
        mx1 = fmaxf(mx1, __shfl_xor_sync(0xFFFFFFFF, mx1, 1));
        mx1 = fmaxf(mx1, __shfl_xor_sync(0xFFFFFFFF, mx1, 2));
        float mn0 = fmaxf(mrow[0], mx0);
        float mn1 = fmaxf(mrow[1], mx1);
        float al0 = fast_exp(mrow[0] - mn0);
        float al1 = fast_exp(mrow[1] - mn1);
        mrow[0] = mn0; mrow[1] = mn1;

        float sum0 = 0.0f, sum1 = 0.0f;
        #pragma unroll
        for (int j = 0; j < 8; ++j) {
            s[j][0] = fast_exp(s[j][0] - mn0); sum0 += s[j][0];
            s[j][1] = fast_exp(s[j][1] - mn0); sum0 += s[j][1];
            s[j][2] = fast_exp(s[j][2] - mn1); sum1 += s[j][2];
            s[j][3] = fast_exp(s[j][3] - mn1); sum1 += s[j][3];
        }
        sum0 += __shfl_xor_sync(0xFFFFFFFF, sum0, 1);
        sum0 += __shfl_xor_sync(0xFFFFFFFF, sum0, 2);
        sum1 += __shfl_xor_sync(0xFFFFFFFF, sum1, 1);
        sum1 += __shfl_xor_sync(0xFFFFFFFF, sum1, 2);
        lrow[0] = lrow[0] * al0 + sum0;
        lrow[1] = lrow[1] * al1 + sum1;

        #pragma unroll
        for (int j = 0; j < 8; ++j) {
            acc[j][0] *= al0; acc[j][1] *= al0;
            acc[j][2] *= al1; acc[j][3] *= al1;
        }

        #pragma unroll
        for (int k2 = 0; k2 < 4; ++k2) {
            uint32_t pa[4];
            pa[0] = pack_f16(s[2*k2][0],   s[2*k2][1]);
            pa[1] = pack_f16(s[2*k2][2],   s[2*k2][3]);
            pa[2] = pack_f16(s[2*k2+1][0], s[2*k2+1][1]);
            pa[3] = pack_f16(s[2*k2+1][2], s[2*k2+1][3]);
            #pragma unroll
            for (int np = 0; np < 4; ++np) {
                uint32_t vv[4];
                uint32_t vaddr = stage + vRow + k2 * (16 * 144) + np * 32;
                LDSM4T(vv[0], vv[1], vv[2], vv[3], vaddr + AT_V);
                MMA_F16(acc[2*np],   pa, vv);
                MMA_F16(acc[2*np+1], pa, vv + 2);
            }
        }
    }

    const float inv0 = 1.0f / lrow[0];
    const float inv1 = 1.0f / lrow[1];
    const int row0 = q0 + m0 + grp;
    const size_t ob0 = (size_t)(bS + row0) * DC + hoff;
    const size_t ob1 = (size_t)(bS + row0 + 8) * DC + hoff;
    #pragma unroll
    for (int j = 0; j < 8; ++j) {
        int col = j * 8 + qd * 2;
        *(uint32_t*)&O[ob0 + col] = pack_f16(acc[j][0] * inv0, acc[j][1] * inv0);
        *(uint32_t*)&O[ob1 + col] = pack_f16(acc[j][2] * inv1, acc[j][3] * inv1);
    }
}

// ---------------------------------------------------------------------------
// Launch
// ---------------------------------------------------------------------------
extern "C" void kernel_launch(void* const* d_in, const int* in_sizes, int n_in,
                              void* d_out, int out_size) {
    const float* x     = (const float*)d_in[0];
    const float* CQ_w  = (const float*)d_in[1];
    const float* CQ_b  = (const float*)d_in[2];
    const float* CQC_w = (const float*)d_in[3];
    const float* CQC_b = (const float*)d_in[4];
    const float* CQR_w = (const float*)d_in[5];
    const float* CQR_b = (const float*)d_in[6];
    const float* CKV_w = (const float*)d_in[7];
    const float* CKV_b = (const float*)d_in[8];
    const float* CKR_w = (const float*)d_in[9];
    const float* CKR_b = (const float*)d_in[10];
    const float* CKC_w = (const float*)d_in[11];
    const float* CKC_b = (const float*)d_in[12];
    const float* CV_w  = (const float*)d_in[13];
    const float* CV_b  = (const float*)d_in[14];
    const float* OUT_w = (const float*)d_in[15];
    const float* OUT_b = (const float*)d_in[16];
    float* out = (float*)d_out;

    __half *xp, *wh, *cqkv, *qp, *kp, *vp, *op;
    float *qr;
    cudaGetSymbolAddress((void**)&xp,   g_x);
    cudaGetSymbolAddress((void**)&wh,   g_wh);
    cudaGetSymbolAddress((void**)&cqkv, g_cqkv);
    cudaGetSymbolAddress((void**)&qp,   g_q);
    cudaGetSymbolAddress((void**)&kp,   g_k);
    cudaGetSymbolAddress((void**)&vp,   g_v);
    cudaGetSymbolAddress((void**)&op,   g_o);
    cudaGetSymbolAddress((void**)&qr,   g_qr);

    cudaFuncSetAttribute(gemm_tiles,
                         cudaFuncAttributeMaxDynamicSharedMemorySize, GEMM_SMEM);
    cudaFuncSetAttribute(attn_mma,
                         cudaFuncAttributeMaxDynamicSharedMemorySize, ATTN_SMEM);

    cvt_x<<<(M * 2048 / 4 + 255) / 256, 256>>>(x, xp, M * 2048 / 4);
    cvt_weights<<<((int)QB7 + 255) / 256, 256>>>(CQ_w, CKV_w, CQR_w, CKR_w,
                                                 CQC_w, CKC_w, CV_w, OUT_w, wh);

    dim3 blk(512);
    const int GY = M / 256;   // 32 row tiles of 256

    auto mkTile = [](const __half* Ah, int lda, const __half* Wh,
                     const float* bias, float* Cf, int ldc,
                     void* Ch, int ldh, int mode, float scale) {
        TileP t;
        t.Ah = Ah; t.Wh = Wh; t.bias = bias;
        t.Cf = Cf; t.Ch = Ch;
        t.lda = lda; t.ldc = ldc; t.ldh = ldh; t.mode = mode; t.scale = scale;
        return t;
    };

    // launch A: CQ | CKV | CQR | CKR  (K = 2048, 10 column tiles)
    {
        TileArr16 ta;
        for (int t = 0; t < 4; ++t)   // cq -> fp16, cqkv cols [0,512)
            ta.t[t] = mkTile(xp, 2048, wh + OFF_Q + (size_t)t*128*2048,
                             CQ_b + t*128, nullptr, 0,
                             cqkv + t*128, 1024, 1|4, 1.0f);
        for (int t = 0; t < 4; ++t)   // ckv -> fp16, cqkv cols [512,1024)
            ta.t[4+t] = mkTile(xp, 2048, wh + OFF_KV + (size_t)t*128*2048,
                             CKV_b + t*128, nullptr, 0,
                             cqkv + 512 + t*128, 1024, 1|4, 1.0f);
        ta.t[8] = mkTile(xp, 2048, wh + OFF_QR,
                         CQR_b, qr, 256, nullptr, 0, 2, 1.0f);
        ta.t[9] = mkTile(xp, 2048, wh + OFF_KR,
                         CKR_b, qr + 128, 256, nullptr, 0, 2, 1.0f);
        gemm_tiles<<<dim3(10, GY), blk, GEMM_SMEM>>>(ta, 2048);
    }

    // launch B: CQC | CKC | CV  (K = 512, 10 column tiles)
    {
        TileArr16 ta;
        for (int t = 0; t < 3; ++t)   // cqc -> Q fp16, gelu*0.125
            ta.t[t] = mkTile(cqkv, 1024, wh + OFF_QC + (size_t)t*128*512,
                             CQC_b + t*128, nullptr, 0,
                             qp + t*128, 512, 1|4, 0.125f);
        for (int t = 0; t < 3; ++t)   // ckc -> K fp16, gelu
            ta.t[3+t] = mkTile(cqkv + 512, 1024, wh + OFF_KC + (size_t)t*128*512,
                             CKC_b + t*128, nullptr, 0,
                             kp + t*128, 512, 1|4, 1.0f);
        for (int t = 0; t < 4; ++t)   // V -> fp16 (no gelu)
            ta.t[6+t] = mkTile(cqkv + 512, 1024, wh + OFF_V + (size_t)t*128*512,
                             CV_b + t*128, nullptr, 0,
                             vp + t*128, 512, 4, 1.0f);
        gemm_tiles<<<dim3(10, GY), blk, GEMM_SMEM>>>(ta, 512);
    }

    // rope columns [384,512) of Q/K
    rope_planes<<<(M * 64 + 255) / 256, 256>>>(qr, qp, kp);

    // causal flash attention -> fp16 O
    attn_mma<<<dim3(S/128, H, B), dim3(256), ATTN_SMEM>>>(qp, kp, vp, op);

    // launch C: OUT  (K = 512, 16 column tiles)
    {
        TileArr16 ta;
        for (int t = 0; t < 16; ++t)
            ta.t[t] = mkTile(op, 512, wh + OFF_OUT + (size_t)t*128*512,
                             OUT_b + t*128, out + t*128, 2048,
                             nullptr, 0, 2, 1.0f);
        gemm_tiles<<<dim3(16, GY), blk, GEMM_SMEM>>>(ta, 512);
    }
}

// round 16
// speedup vs baseline: 1.0219x; 1.0219x over previous
#include <cuda_runtime.h>
#include <cuda_fp16.h>
#include <math.h>
#include <stdint.h>

// ---------------------------------------------------------------------------
// Problem constants
// ---------------------------------------------------------------------------
constexpr int B     = 4;
constexpr int S     = 2048;
constexpr int EMBED = 2048;
constexpr int DC    = 512;     // D_COMPR
constexpr int DR    = 128;     // D_ROPE
constexpr int DCC   = DC - DR; // 384
constexpr int H     = 8;
constexpr int HD    = 64;      // head dim
constexpr int M     = B * S;   // 8192 rows

// weight offsets (elements) inside g_wh (single fp16 plane)
constexpr size_t OFF_Q   = 0;
constexpr size_t OFF_KV  = OFF_Q   + 512 * 2048;
constexpr size_t OFF_QR  = OFF_KV  + 512 * 2048;
constexpr size_t OFF_KR  = OFF_QR  + 128 * 2048;
constexpr size_t OFF_QC  = OFF_KR  + 128 * 2048;
constexpr size_t OFF_KC  = OFF_QC  + 384 * 512;
constexpr size_t OFF_V   = OFF_KC  + 384 * 512;
constexpr size_t OFF_OUT = OFF_V   + 512 * 512;
constexpr size_t W_TOTAL = OFF_OUT + 2048 * 512;

// ---------------------------------------------------------------------------
// Scratch (device globals; allocation is forbidden)
// ---------------------------------------------------------------------------
__device__ __align__(16) __half g_x [(size_t)M * 2048];
__device__ __align__(16) __half g_wh[W_TOTAL];
__device__ __align__(16) __half g_cqkv[(size_t)M * 1024];
__device__ __align__(16) __half g_q [(size_t)M * 512];
__device__ __align__(16) __half g_k [(size_t)M * 512];
__device__ __align__(16) __half g_v [(size_t)M * 512];
__device__ __align__(16) __half g_o [(size_t)M * 512];
__device__ float g_qr [M * 256];       // cols 0-127: cqr, 128-255: ckr (pre-rope)

__device__ __forceinline__ float gelu_exact(float v) {
    return 0.5f * v * (1.0f + erff(v * 0.70710678118654752f));
}

// fp32 pair -> f16x2
__device__ __forceinline__ uint32_t pack_f16(float e0, float e1) {
    uint32_t h;
    asm("cvt.rn.f16x2.f32 %0, %1, %2;" : "=r"(h) : "f"(e1), "f"(e0));
    return h;
}

// FMA-pipe exp (no MUFU): exp(x) for x <= 0, clamped at -80.
__device__ __forceinline__ float fast_exp(float x) {
    x = fmaxf(x, -80.0f);
    float t = fmaf(x, 1.4426950408889634f, 12582912.0f);
    float i = t - 12582912.0f;
    float f = fmaf(x, 1.4426950408889634f, -i);
    float p = 1.3333558146e-3f;
    p = fmaf(p, f, 9.6181291076e-3f);
    p = fmaf(p, f, 5.5504108665e-2f);
    p = fmaf(p, f, 2.4022650696e-1f);
    p = fmaf(p, f, 6.9314718056e-1f);
    p = fmaf(p, f, 1.0f);
    return __int_as_float(__float_as_int(p) +
                          ((__float_as_int(t) - 0x4B400000) << 23));
}

__device__ __forceinline__ uint32_t smem_u32(const void* p) {
    uint32_t a;
    asm("{ .reg .u64 t; cvta.to.shared.u64 t, %1; cvt.u32.u64 %0, t; }"
        : "=r"(a) : "l"(p));
    return a;
}

#define CP16(dst, src) \
    asm volatile("cp.async.cg.shared.global [%0], [%1], 16;" \
                 :: "r"(dst), "l"(src) : "memory")
#define CP_COMMIT() asm volatile("cp.async.commit_group;" ::: "memory")
#define CP_WAIT0()  asm volatile("cp.async.wait_group 0;" ::: "memory")
#define CP_WAIT2()  asm volatile("cp.async.wait_group 2;" ::: "memory")

#define LDSM4(r0, r1, r2, r3, addr) \
    asm volatile("ldmatrix.sync.aligned.m8n8.x4.shared.b16 {%0,%1,%2,%3}, [%4];" \
                 : "=r"(r0), "=r"(r1), "=r"(r2), "=r"(r3) : "r"(addr))
#define LDSM4T(r0, r1, r2, r3, addr) \
    asm volatile("ldmatrix.sync.aligned.m8n8.x4.trans.shared.b16 {%0,%1,%2,%3}, [%4];" \
                 : "=r"(r0), "=r"(r1), "=r"(r2), "=r"(r3) : "r"(addr))

#define MMA_F16(d, a, b) \
    asm volatile("mma.sync.aligned.m16n8k16.row.col.f32.f16.f16.f32 " \
                 "{%0,%1,%2,%3},{%4,%5,%6,%7},{%8,%9},{%0,%1,%2,%3};" \
                 : "+f"((d)[0]), "+f"((d)[1]), "+f"((d)[2]), "+f"((d)[3]) \
                 : "r"((a)[0]), "r"((a)[1]), "r"((a)[2]), "r"((a)[3]), \
                   "r"((b)[0]), "r"((b)[1]))

// ---------------------------------------------------------------------------
// fp32 -> fp16 (x)
// ---------------------------------------------------------------------------
__global__ void cvt_x(const float* __restrict__ src,
                      __half* __restrict__ dst, int n4) {
    int i = blockIdx.x * blockDim.x + threadIdx.x;
    if (i >= n4) return;
    float4 v = ((const float4*)src)[i];
    ((uint2*)dst)[i] = make_uint2(pack_f16(v.x, v.y), pack_f16(v.z, v.w));
}

// ---------------------------------------------------------------------------
// All 8 weights -> g_wh (single fp16 plane) in one launch
// ---------------------------------------------------------------------------
constexpr size_t QB0 = OFF_KV  / 4;
constexpr size_t QB1 = OFF_QR  / 4;
constexpr size_t QB2 = OFF_KR  / 4;
constexpr size_t QB3 = OFF_QC  / 4;
constexpr size_t QB4 = OFF_KC  / 4;
constexpr size_t QB5 = OFF_V   / 4;
constexpr size_t QB6 = OFF_OUT / 4;
constexpr size_t QB7 = W_TOTAL / 4;

__global__ void cvt_weights(const float* __restrict__ s0, const float* __restrict__ s1,
                            const float* __restrict__ s2, const float* __restrict__ s3,
                            const float* __restrict__ s4, const float* __restrict__ s5,
                            const float* __restrict__ s6, const float* __restrict__ s7,
                            __half* __restrict__ wh) {
    size_t i = (size_t)blockIdx.x * blockDim.x + threadIdx.x;
    if (i >= QB7) return;
    const float* src; size_t base;
    if      (i < QB0) { src = s0; base = 0;   }
    else if (i < QB1) { src = s1; base = QB0; }
    else if (i < QB2) { src = s2; base = QB1; }
    else if (i < QB3) { src = s3; base = QB2; }
    else if (i < QB4) { src = s4; base = QB3; }
    else if (i < QB5) { src = s5; base = QB4; }
    else if (i < QB6) { src = s6; base = QB5; }
    else              { src = s7; base = QB6; }
    float4 v = ((const float4*)src)[i - base];
    ((uint2*)wh)[i] = make_uint2(pack_f16(v.x, v.y), pack_f16(v.z, v.w));
}

// ---------------------------------------------------------------------------
// Fused multi-tile GEMM via mma.sync (single fp16, fp32 accumulate)
// 256x128 CTA tile, 512 threads (16 warps, 4m x 4n, 64x32 warp tile),
// BK=32, 4-stage cp.async pipeline, ONE __syncthreads per kt, 120 KB smem.
// Inner loop: all B fragments (both k16) batched up front, A fragments for
// both k16 loaded per mt -> deep independent LDSM window before MMAs.
// mode bits: 1 = GELU, 2 = write fp32 C, 4 = write fp16 plane (Ch).
// ---------------------------------------------------------------------------
struct TileP {
    const __half *Ah, *Wh;
    const float* bias;
    float* Cf;
    void *Ch;
    int lda, ldc, ldh, mode;
    float scale;
};
struct TileArr16 { TileP t[16]; };

constexpr int SM_AH = 0;          // 256 rows * 80B = 20480
constexpr int SM_BH = 20480;      // 128 rows * 80B = 10240
constexpr int SM_STAGE = 30720;
constexpr int GEMM_SMEM = 4 * SM_STAGE;   // 122880

__global__ void __launch_bounds__(512)
gemm_tiles(TileArr16 ta, int K) {
    const TileP tp = ta.t[blockIdx.x];

    extern __shared__ char smem[];
    const uint32_t sb = smem_u32(smem);

    const int tid    = threadIdx.x;
    const int lane   = tid & 31;
    const int wid    = tid >> 5;
    const int warp_m = wid >> 2;        // 0..3
    const int warp_n = wid & 3;         // 0..3
    const int bm     = blockIdx.y * 256;

    // staging: A (2 threads/row, 32B each), B (4 threads/row, 16B each)
    const int arow = tid >> 1;                       // 0..255
    const int acb  = (tid & 1) * 32;                 // byte chunk in 64B row
    const __half* gA = tp.Ah + (size_t)(bm + arow) * tp.lda + acb / 2;
    const uint32_t sA = (uint32_t)(arow * 80 + acb);

    const int brow = tid >> 2;                       // 0..127
    const int bcb  = (tid & 3) * 16;
    const __half* gB = tp.Wh + (size_t)brow * K + bcb / 2;
    const uint32_t sB = (uint32_t)(brow * 80 + bcb);

    const uint32_t aBase = (uint32_t)((warp_m * 64 + (lane & 15)) * 80 +
                                      ((lane >> 4) << 4));
    const uint32_t bBase = (uint32_t)((warp_n * 32 + (lane & 7) +
                                       ((lane & 16) >> 1)) * 80 +
                                      (((lane >> 3) & 1) << 4));

    float d[4][4][4];
    #pragma unroll
    for (int i = 0; i < 4; ++i)
        #pragma unroll
        for (int j = 0; j < 4; ++j)
            #pragma unroll
            for (int k = 0; k < 4; ++k) d[i][j][k] = 0.0f;

    auto load_stage = [&](int s, int kt) {
        const uint32_t sbase = sb + s * SM_STAGE;
        const int ge = kt * 32;        // element offset
        CP16(sbase + SM_AH + sA,      gA + ge);
        CP16(sbase + SM_AH + sA + 16, gA + ge + 8);
        CP16(sbase + SM_BH + sB,      gB + ge);
    };

    const int KT = K >> 5;   // >= 16 always
    load_stage(0, 0); CP_COMMIT();
    load_stage(1, 1); CP_COMMIT();
    load_stage(2, 2); CP_COMMIT();

    for (int kt = 0; kt < KT; ++kt) {
        CP_WAIT2();          // stage kt landed (<=2 groups outstanding)
        __syncthreads();     // all warps done with stage kt-1 (overwrite target)

        if (kt + 3 < KT) load_stage((kt + 3) & 3, kt + 3);
        CP_COMMIT();

        const uint32_t stage = sb + (kt & 3) * SM_STAGE;

        // ---- batch all B fragments for both k16 steps (4 LDSM in flight) --
        uint32_t bh[2][4][2];
        #pragma unroll
        for (int k16 = 0; k16 < 2; ++k16)
            #pragma unroll
            for (int np = 0; np < 2; ++np) {
                uint32_t addr = stage + bBase + np * (16 * 80) + k16 * 32;
                LDSM4(bh[k16][2*np][0], bh[k16][2*np][1],
                      bh[k16][2*np+1][0], bh[k16][2*np+1][1], addr + SM_BH);
            }

        // ---- per mt: both k16 A fragments, then 8 MMAs ----
        #pragma unroll
        for (int mt = 0; mt < 4; ++mt) {
            uint32_t addr = stage + aBase + mt * (16 * 80);
            uint32_t a0[4], a1[4];
            LDSM4(a0[0], a0[1], a0[2], a0[3], addr + SM_AH);
            LDSM4(a1[0], a1[1], a1[2], a1[3], addr + SM_AH + 32);
            #pragma unroll
            for (int nt = 0; nt < 4; ++nt)
                MMA_F16(d[mt][nt], a0, bh[0][nt]);
            #pragma unroll
            for (int nt = 0; nt < 4; ++nt)
                MMA_F16(d[mt][nt], a1, bh[1][nt]);
        }
    }

    // ------------------------- epilogue -------------------------
    const int grp  = lane >> 2;
    const int qd   = lane & 3;
    const int mode = tp.mode;
    const float sc = tp.scale;
    #pragma unroll
    for (int mt = 0; mt < 4; ++mt) {
        const int r0 = bm + warp_m * 64 + mt * 16 + grp;
        const int r1 = r0 + 8;
        #pragma unroll
        for (int nt = 0; nt < 4; ++nt) {
            const int col = warp_n * 32 + nt * 8 + qd * 2;
            float2 bb = *(const float2*)&tp.bias[col];
            float v00 = d[mt][nt][0] + bb.x;
            float v01 = d[mt][nt][1] + bb.y;
            float v10 = d[mt][nt][2] + bb.x;
            float v11 = d[mt][nt][3] + bb.y;
            if (mode & 1) {
                v00 = gelu_exact(v00); v01 = gelu_exact(v01);
                v10 = gelu_exact(v10); v11 = gelu_exact(v11);
            }
            v00 *= sc; v01 *= sc; v10 *= sc; v11 *= sc;
            if (mode & 2) {
                *(float2*)&tp.Cf[(size_t)r0 * tp.ldc + col] = make_float2(v00, v01);
                *(float2*)&tp.Cf[(size_t)r1 * tp.ldc + col] = make_float2(v10, v11);
            }
            if (mode & 4) {
                __half* Chp = (__half*)tp.Ch;
                *(uint32_t*)&Chp[(size_t)r0 * tp.ldh + col] = pack_f16(v00, v01);
                *(uint32_t*)&Chp[(size_t)r1 * tp.ldh + col] = pack_f16(v10, v11);
            }
        }
    }
}

// ---------------------------------------------------------------------------
// Rope-only builder for Q/K columns [384, 512). Q/K single fp16.
// ---------------------------------------------------------------------------
__global__ void rope_planes(const float* __restrict__ qr,
                            __half* __restrict__ qp, __half* __restrict__ kp) {
    int idx = blockIdx.x * blockDim.x + threadIdx.x;   // M*64
    if (idx >= M * 64) return;
    int m  = idx >> 6;
    int jp = (idx & 63) * 2;
    int s  = m & (S - 1);

    float vq[2], vk[2];
    #pragma unroll
    for (int e = 0; e < 2; ++e) {
        int jj = jp + e;
        int i  = jj & 63;
        float invf = expf(-(float)i * (9.2103403719761836f / 64.0f));
        float ang  = (float)s * invf;
        float sv, cv; sincosf(ang, &sv, &cv);
        float xq = qr[m * 256 + jj];
        float xk = qr[m * 256 + 128 + jj];
        float rq, rk;
        if (jj < 64) { rq = -qr[m * 256 + jj + 64]; rk = -qr[m * 256 + 128 + jj + 64]; }
        else         { rq =  qr[m * 256 + jj - 64]; rk =  qr[m * 256 + 128 + jj - 64]; }
        vq[e] = gelu_exact(xq * cv + rq * sv) * 0.125f;
        vk[e] = gelu_exact(xk * cv + rk * sv);
    }
    size_t o = (size_t)m * DC + DCC + jp;
    *(uint32_t*)&qp[o] = pack_f16(vq[0], vq[1]);
    *(uint32_t*)&kp[o] = pack_f16(vk[0], vk[1]);
}

// ---------------------------------------------------------------------------
// Flash attention via mma.sync, single fp16 Q/K/P/V, fp32 accum/softmax.
// 2-stage KV pipeline, 55.3 KB smem. qt reversed for load balance.
// ---------------------------------------------------------------------------
constexpr int AT_Q    = 0;                 // 128 rows * 144B = 18432
constexpr int AT_ST0  = 18432;
constexpr int AT_K    = 0;                 // within stage: 64 rows * 144B = 9216
constexpr int AT_V    = 9216;
constexpr int AT_STSZ = 18432;
constexpr int ATTN_SMEM = AT_ST0 + 2 * AT_STSZ;   // 55296

__global__ void __launch_bounds__(256)
attn_mma(const __half* __restrict__ Qp, const __half* __restrict__ Kp,
         const __half* __restrict__ Vp, __half* __restrict__ O) {
    extern __shared__ char smem[];
    const uint32_t sb = smem_u32(smem);

    const int qt = gridDim.x - 1 - blockIdx.x;   // heavy tiles first
    const int h = blockIdx.y, b = blockIdx.z;
    const int q0 = qt * 128;
    const int tid  = threadIdx.x;
    const int lane = tid & 31;
    const int wid  = tid >> 5;
    const int m0   = wid * 16;
    const int grp  = lane >> 2;
    const int qd   = lane & 3;
    const int bS   = b * S;
    const size_t hoff = (size_t)h * HD;

    auto load_kv = [&](int kt, int buf) {
        const uint32_t stage = sb + AT_ST0 + buf * AT_STSZ;
        int r  = tid >> 2;
        int ch = (tid & 3) * 2;
        size_t g = (size_t)(bS + kt * 64 + r) * DC + hoff + ch * 8;
        uint32_t sdst = stage + r * 144 + ch * 16;
        #pragma unroll
        for (int c = 0; c < 2; ++c) {
            CP16(sdst + AT_K + c * 16, Kp + g + c * 8);
            CP16(sdst + AT_V + c * 16, Vp + g + c * 8);
        }
    };

    {
        int r  = tid >> 1;
        int ch = (tid & 1) * 4;
        size_t g = (size_t)(bS + q0 + r) * DC + hoff + ch * 8;
        uint32_t sdst = sb + AT_Q + r * 144 + ch * 16;
        #pragma unroll
        for (int c = 0; c < 4; ++c)
            CP16(sdst + c * 16, Qp + g + c * 8);
    }
    load_kv(0, 0);
    CP_COMMIT();

    float mrow[2] = {-1e30f, -1e30f};
    float lrow[2] = {0.0f, 0.0f};
    float acc[8][4];
    #pragma unroll
    for (int j = 0; j < 8; ++j)
        #pragma unroll
        for (int c = 0; c < 4; ++c) acc[j][c] = 0.0f;

    const uint32_t aBase = sb + AT_Q + (m0 + (lane & 15)) * 144 +
                           ((lane >> 4) << 4);
    const uint32_t bRow  = ((lane & 7) + ((lane & 16) >> 1)) * 144 +
                           (((lane >> 3) & 1) << 4);
    const uint32_t vRow  = (lane & 15) * 144 + ((lane >> 4) << 4);

    const int kt_end = 2 * qt + 1;
    for (int kt = 0; kt <= kt_end; ++kt) {
        CP_WAIT0();
        __syncthreads();
        if (kt < kt_end) { load_kv(kt + 1, (kt + 1) & 1); }
        CP_COMMIT();

        const uint32_t stage = sb + AT_ST0 + (kt & 1) * AT_STSZ;
        const int k0 = kt * 64;

        float s[8][4];
        #pragma unroll
        for (int j = 0; j < 8; ++j)
            #pragma unroll
            for (int c = 0; c < 4; ++c) s[j][c] = 0.0f;

        #pragma unroll
        for (int k16 = 0; k16 < 4; ++k16) {
            uint32_t qh[4];
            LDSM4(qh[0], qh[1], qh[2], qh[3], aBase + k16 * 32);
            #pragma unroll
            for (int np = 0; np < 4; ++np) {
                uint32_t kk[4];
                uint32_t baddr = stage + bRow + np * (16 * 144) + k16 * 32;
                LDSM4(kk[0], kk[1], kk[2], kk[3], baddr + AT_K);
                MMA_F16(s[2*np],   qh, kk);
                MMA_F16(s[2*np+1], qh, kk + 2);
            }
        }

        const int row0 = q0 + m0 + grp;
        if (k0 + 63 > q0 + m0) {
            #pragma unroll
            for (int j = 0; j < 8; ++j) {
                int kg = k0 + j * 8 + qd * 2;
                if (kg     > row0)     s[j][0] = -1e30f;
                if (kg + 1 > row0)     s[j][1] = -1e30f;
                if (kg     > row0 + 8) s[j][2] = -1e30f;
                if (kg + 1 > row0 + 8) s[j][3] = -1e30f;
            }
        }

        float mx0 = -1e30f, mx1 = -1e30f;
        #pragma unroll
        for (int j = 0; j < 8; ++j) {
            mx0 = fmaxf(mx0, fmaxf(s[j][0], s[j][1]));
            mx1 = fmaxf(mx1, fmaxf(s[j][2], s[j][3]));
        }
        mx0 = fmaxf(mx0, __shfl_xor_sync(0xFFFFFFFF, mx0, 1));
        mx0 = fmaxf(mx0, __shfl_xor_sync(0xFFFFFFFF, mx0, 2));
        mx1 = fmaxf(mx1, __shfl_xor_sync(0xFFFFFFFF, mx1, 1));
        mx1 = fmaxf(mx1, __shfl_xor_sync(0xFFFFFFFF, mx1, 2));
        float mn0 = fmaxf(mrow[0], mx0);
        float mn1 = fmaxf(mrow[1], mx1);
        float al0 = fast_exp(mrow[0] - mn0);
        float al1 = fast_exp(mrow[1] - mn1);
        mrow[0] = mn0; mrow[1] = mn1;

        float sum0 = 0.0f, sum1 = 0.0f;
        #pragma unroll
        for (int j = 0; j < 8; ++j) {
            s[j][0] = fast_exp(s[j][0] - mn0); sum0 += s[j][0];
            s[j][1] = fast_exp(s[j][1] - mn0); sum0 += s[j][1];
            s[j][2] = fast_exp(s[j][2] - mn1); sum1 += s[j][2];
            s[j][3] = fast_exp(s[j][3] - mn1); sum1 += s[j][3];
        }
        sum0 += __shfl_xor_sync(0xFFFFFFFF, sum0, 1);
        sum0 += __shfl_xor_sync(0xFFFFFFFF, sum0, 2);
        sum1 += __shfl_xor_sync(0xFFFFFFFF, sum1, 1);
        sum1 += __shfl_xor_sync(0xFFFFFFFF, sum1, 2);
        lrow[0] = lrow[0] * al0 + sum0;
        lrow[1] = lrow[1] * al1 + sum1;

        #pragma unroll
        for (int j = 0; j < 8; ++j) {
            acc[j][0] *= al0; acc[j][1] *= al0;
            acc[j][2] *= al1; acc[j][3] *= al1;
        }

        #pragma unroll
        for (int k2 = 0; k2 < 4; ++k2) {
            uint32_t pa[4];
            pa[0] = pack_f16(s[2*k2][0],   s[2*k2][1]);
            pa[1] = pack_f16(s[2*k2][2],   s[2*k2][3]);
            pa[2] = pack_f16(s[2*k2+1][0], s[2*k2+1][1]);
            pa[3] = pack_f16(s[2*k2+1][2], s[2*k2+1][3]);
            #pragma unroll
            for (int np = 0; np < 4; ++np) {
                uint32_t vv[4];
                uint32_t vaddr = stage + vRow + k2 * (16 * 144) + np * 32;
                LDSM4T(vv[0], vv[1], vv[2], vv[3], vaddr + AT_V);
                MMA_F16(acc[2*np],   pa, vv);
                MMA_F16(acc[2*np+1], pa, vv + 2);
            }
        }
    }

    const float inv0 = 1.0f / lrow[0];
    const float inv1 = 1.0f / lrow[1];
    const int row0 = q0 + m0 + grp;
    const size_t ob0 = (size_t)(bS + row0) * DC + hoff;
    const size_t ob1 = (size_t)(bS + row0 + 8) * DC + hoff;
    #pragma unroll
    for (int j = 0; j < 8; ++j) {
        int col = j * 8 + qd * 2;
        *(uint32_t*)&O[ob0 + col] = pack_f16(acc[j][0] * inv0, acc[j][1] * inv0);
        *(uint32_t*)&O[ob1 + col] = pack_f16(acc[j][2] * inv1, acc[j][3] * inv1);
    }
}

// ---------------------------------------------------------------------------
// Launch
// ---------------------------------------------------------------------------
extern "C" void kernel_launch(void* const* d_in, const int* in_sizes, int n_in,
                              void* d_out, int out_size) {
    const float* x     = (const float*)d_in[0];
    const float* CQ_w  = (const float*)d_in[1];
    const float* CQ_b  = (const float*)d_in[2];
    const float* CQC_w = (const float*)d_in[3];
    const float* CQC_b = (const float*)d_in[4];
    const float* CQR_w = (const float*)d_in[5];
    const float* CQR_b = (const float*)d_in[6];
    const float* CKV_w = (const float*)d_in[7];
    const float* CKV_b = (const float*)d_in[8];
    const float* CKR_w = (const float*)d_in[9];
    const float* CKR_b = (const float*)d_in[10];
    const float* CKC_w = (const float*)d_in[11];
    const float* CKC_b = (const float*)d_in[12];
    const float* CV_w  = (const float*)d_in[13];
    const float* CV_b  = (const float*)d_in[14];
    const float* OUT_w = (const float*)d_in[15];
    const float* OUT_b = (const float*)d_in[16];
    float* out = (float*)d_out;

    __half *xp, *wh, *cqkv, *qp, *kp, *vp, *op;
    float *qr;
    cudaGetSymbolAddress((void**)&xp,   g_x);
    cudaGetSymbolAddress((void**)&wh,   g_wh);
    cudaGetSymbolAddress((void**)&cqkv, g_cqkv);
    cudaGetSymbolAddress((void**)&qp,   g_q);
    cudaGetSymbolAddress((void**)&kp,   g_k);
    cudaGetSymbolAddress((void**)&vp,   g_v);
    cudaGetSymbolAddress((void**)&op,   g_o);
    cudaGetSymbolAddress((void**)&qr,   g_qr);

    cudaFuncSetAttribute(gemm_tiles,
                         cudaFuncAttributeMaxDynamicSharedMemorySize, GEMM_SMEM);
    cudaFuncSetAttribute(attn_mma,
                         cudaFuncAttributeMaxDynamicSharedMemorySize, ATTN_SMEM);

    cvt_x<<<(M * 2048 / 4 + 255) / 256, 256>>>(x, xp, M * 2048 / 4);
    cvt_weights<<<((int)QB7 + 255) / 256, 256>>>(CQ_w, CKV_w, CQR_w, CKR_w,
                                                 CQC_w, CKC_w, CV_w, OUT_w, wh);

    dim3 blk(512);
    const int GY = M / 256;   // 32 row tiles of 256

    auto mkTile = [](const __half* Ah, int lda, const __half* Wh,
                     const float* bias, float* Cf, int ldc,
                     void* Ch, int ldh, int mode, float scale) {
        TileP t;
        t.Ah = Ah; t.Wh = Wh; t.bias = bias;
        t.Cf = Cf; t.Ch = Ch;
        t.lda = lda; t.ldc = ldc; t.ldh = ldh; t.mode = mode; t.scale = scale;
        return t;
    };

    // launch A: CQ | CKV | CQR | CKR  (K = 2048, 10 column tiles)
    {
        TileArr16 ta;
        for (int t = 0; t < 4; ++t)   // cq -> fp16, cqkv cols [0,512)
            ta.t[t] = mkTile(xp, 2048, wh + OFF_Q + (size_t)t*128*2048,
                             CQ_b + t*128, nullptr, 0,
                             cqkv + t*128, 1024, 1|4, 1.0f);
        for (int t = 0; t < 4; ++t)   // ckv -> fp16, cqkv cols [512,1024)
            ta.t[4+t] = mkTile(xp, 2048, wh + OFF_KV + (size_t)t*128*2048,
                             CKV_b + t*128, nullptr, 0,
                             cqkv + 512 + t*128, 1024, 1|4, 1.0f);
        ta.t[8] = mkTile(xp, 2048, wh + OFF_QR,
                         CQR_b, qr, 256, nullptr, 0, 2, 1.0f);
        ta.t[9] = mkTile(xp, 2048, wh + OFF_KR,
                         CKR_b, qr + 128, 256, nullptr, 0, 2, 1.0f);
        gemm_tiles<<<dim3(10, GY), blk, GEMM_SMEM>>>(ta, 2048);
    }

    // launch B: CQC | CKC | CV  (K = 512, 10 column tiles)
    {
        TileArr16 ta;
        for (int t = 0; t < 3; ++t)   // cqc -> Q fp16, gelu*0.125
            ta.t[t] = mkTile(cqkv, 1024, wh + OFF_QC + (size_t)t*128*512,
                             CQC_b + t*128, nullptr, 0,
                             qp + t*128, 512, 1|4, 0.125f);
        for (int t = 0; t < 3; ++t)   // ckc -> K fp16, gelu
            ta.t[3+t] = mkTile(cqkv + 512, 1024, wh + OFF_KC + (size_t)t*128*512,
                             CKC_b + t*128, nullptr, 0,
                             kp + t*128, 512, 1|4, 1.0f);
        for (int t = 0; t < 4; ++t)   // V -> fp16 (no gelu)
            ta.t[6+t] = mkTile(cqkv + 512, 1024, wh + OFF_V + (size_t)t*128*512,
                             CV_b + t*128, nullptr, 0,
                             vp + t*128, 512, 4, 1.0f);
        gemm_tiles<<<dim3(10, GY), blk, GEMM_SMEM>>>(ta, 512);
    }

    // rope columns [384,512) of Q/K
    rope_planes<<<(M * 64 + 255) / 256, 256>>>(qr, qp, kp);

    // causal flash attention -> fp16 O
    attn_mma<<<dim3(S/128, H, B), dim3(256), ATTN_SMEM>>>(qp, kp, vp, op);

    // launch C: OUT  (K = 512, 16 column tiles)
    {
        TileArr16 ta;
        for (int t = 0; t < 16; ++t)
            ta.t[t] = mkTile(op, 512, wh + OFF_OUT + (size_t)t*128*512,
                             OUT_b + t*128, out + t*128, 2048,
                             nullptr, 0, 2, 1.0f);
        gemm_tiles<<<dim3(16, GY), blk, GEMM_SMEM>>>(ta, 512);
    }
}

// round 17
// speedup vs baseline: 1.1522x; 1.1275x over previous
#include <cuda_runtime.h>
#include <cuda_fp16.h>
#include <math.h>
#include <stdint.h>

// ---------------------------------------------------------------------------
// Problem constants
// ---------------------------------------------------------------------------
constexpr int B     = 4;
constexpr int S     = 2048;
constexpr int EMBED = 2048;
constexpr int DC    = 512;     // D_COMPR
constexpr int DR    = 128;     // D_ROPE
constexpr int DCC   = DC - DR; // 384
constexpr int H     = 8;
constexpr int HD    = 64;      // head dim
constexpr int M     = B * S;   // 8192 rows

// weight offsets (elements) inside g_wh (single fp16 plane)
constexpr size_t OFF_Q   = 0;
constexpr size_t OFF_KV  = OFF_Q   + 512 * 2048;
constexpr size_t OFF_QR  = OFF_KV  + 512 * 2048;
constexpr size_t OFF_KR  = OFF_QR  + 128 * 2048;
constexpr size_t OFF_QC  = OFF_KR  + 128 * 2048;
constexpr size_t OFF_KC  = OFF_QC  + 384 * 512;
constexpr size_t OFF_V   = OFF_KC  + 384 * 512;
constexpr size_t OFF_OUT = OFF_V   + 512 * 512;
constexpr size_t W_TOTAL = OFF_OUT + 2048 * 512;

// ---------------------------------------------------------------------------
// Scratch (device globals; allocation is forbidden)
// ---------------------------------------------------------------------------
__device__ __align__(16) __half g_x [(size_t)M * 2048];
__device__ __align__(16) __half g_wh[W_TOTAL];
__device__ __align__(16) __half g_cqkv[(size_t)M * 1024];
__device__ __align__(16) __half g_q [(size_t)M * 512];
__device__ __align__(16) __half g_k [(size_t)M * 512];
__device__ __align__(16) __half g_v [(size_t)M * 512];
__device__ __align__(16) __half g_o [(size_t)M * 512];
__device__ float g_qr [M * 256];       // cols 0-127: cqr, 128-255: ckr (pre-rope)

__device__ __forceinline__ float gelu_exact(float v) {
    return 0.5f * v * (1.0f + erff(v * 0.70710678118654752f));
}

// fp32 pair -> f16x2
__device__ __forceinline__ uint32_t pack_f16(float e0, float e1) {
    uint32_t h;
    asm("cvt.rn.f16x2.f32 %0, %1, %2;" : "=r"(h) : "f"(e1), "f"(e0));
    return h;
}

// FMA-pipe exp (no MUFU): exp(x) for x <= 0, clamped at -80.
__device__ __forceinline__ float fast_exp(float x) {
    x = fmaxf(x, -80.0f);
    float t = fmaf(x, 1.4426950408889634f, 12582912.0f);
    float i = t - 12582912.0f;
    float f = fmaf(x, 1.4426950408889634f, -i);
    float p = 1.3333558146e-3f;
    p = fmaf(p, f, 9.6181291076e-3f);
    p = fmaf(p, f, 5.5504108665e-2f);
    p = fmaf(p, f, 2.4022650696e-1f);
    p = fmaf(p, f, 6.9314718056e-1f);
    p = fmaf(p, f, 1.0f);
    return __int_as_float(__float_as_int(p) +
                          ((__float_as_int(t) - 0x4B400000) << 23));
}

__device__ __forceinline__ uint32_t smem_u32(const void* p) {
    uint32_t a;
    asm("{ .reg .u64 t; cvta.to.shared.u64 t, %1; cvt.u32.u64 %0, t; }"
        : "=r"(a) : "l"(p));
    return a;
}

#define CP16(dst, src) \
    asm volatile("cp.async.cg.shared.global [%0], [%1], 16;" \
                 :: "r"(dst), "l"(src) : "memory")
#define CP_COMMIT() asm volatile("cp.async.commit_group;" ::: "memory")
#define CP_WAIT0()  asm volatile("cp.async.wait_group 0;" ::: "memory")
#define CP_WAIT2()  asm volatile("cp.async.wait_group 2;" ::: "memory")

#define LDSM4(r0, r1, r2, r3, addr) \
    asm volatile("ldmatrix.sync.aligned.m8n8.x4.shared.b16 {%0,%1,%2,%3}, [%4];" \
                 : "=r"(r0), "=r"(r1), "=r"(r2), "=r"(r3) : "r"(addr))
#define LDSM4T(r0, r1, r2, r3, addr) \
    asm volatile("ldmatrix.sync.aligned.m8n8.x4.trans.shared.b16 {%0,%1,%2,%3}, [%4];" \
                 : "=r"(r0), "=r"(r1), "=r"(r2), "=r"(r3) : "r"(addr))

#define MMA_F16(d, a, b) \
    asm volatile("mma.sync.aligned.m16n8k16.row.col.f32.f16.f16.f32 " \
                 "{%0,%1,%2,%3},{%4,%5,%6,%7},{%8,%9},{%0,%1,%2,%3};" \
                 : "+f"((d)[0]), "+f"((d)[1]), "+f"((d)[2]), "+f"((d)[3]) \
                 : "r"((a)[0]), "r"((a)[1]), "r"((a)[2]), "r"((a)[3]), \
                   "r"((b)[0]), "r"((b)[1]))

// ---------------------------------------------------------------------------
// fp32 -> fp16 (x)
// ---------------------------------------------------------------------------
__global__ void cvt_x(const float* __restrict__ src,
                      __half* __restrict__ dst, int n4) {
    int i = blockIdx.x * blockDim.x + threadIdx.x;
    if (i >= n4) return;
    float4 v = ((const float4*)src)[i];
    ((uint2*)dst)[i] = make_uint2(pack_f16(v.x, v.y), pack_f16(v.z, v.w));
}

// ---------------------------------------------------------------------------
// All 8 weights -> g_wh (single fp16 plane) in one launch
// ---------------------------------------------------------------------------
constexpr size_t QB0 = OFF_KV  / 4;
constexpr size_t QB1 = OFF_QR  / 4;
constexpr size_t QB2 = OFF_KR  / 4;
constexpr size_t QB3 = OFF_QC  / 4;
constexpr size_t QB4 = OFF_KC  / 4;
constexpr size_t QB5 = OFF_V   / 4;
constexpr size_t QB6 = OFF_OUT / 4;
constexpr size_t QB7 = W_TOTAL / 4;

__global__ void cvt_weights(const float* __restrict__ s0, const float* __restrict__ s1,
                            const float* __restrict__ s2, const float* __restrict__ s3,
                            const float* __restrict__ s4, const float* __restrict__ s5,
                            const float* __restrict__ s6, const float* __restrict__ s7,
                            __half* __restrict__ wh) {
    size_t i = (size_t)blockIdx.x * blockDim.x + threadIdx.x;
    if (i >= QB7) return;
    const float* src; size_t base;
    if      (i < QB0) { src = s0; base = 0;   }
    else if (i < QB1) { src = s1; base = QB0; }
    else if (i < QB2) { src = s2; base = QB1; }
    else if (i < QB3) { src = s3; base = QB2; }
    else if (i < QB4) { src = s4; base = QB3; }
    else if (i < QB5) { src = s5; base = QB4; }
    else if (i < QB6) { src = s6; base = QB5; }
    else              { src = s7; base = QB6; }
    float4 v = ((const float4*)src)[i - base];
    ((uint2*)wh)[i] = make_uint2(pack_f16(v.x, v.y), pack_f16(v.z, v.w));
}

// ---------------------------------------------------------------------------
// Fused multi-tile GEMM via mma.sync (single fp16, fp32 accumulate)
// 128x128 CTA tile, 256 threads (8 warps: 2m x 4n, 64x32 warp tile),
// BK=32, 4-stage cp.async pipeline, ONE __syncthreads per kt, 80 KB smem
// -> 2 CTAs/SM (RF: 256 thr x ~128 regs = 32K regs/CTA).
// Inner loop structure byte-identical to the measured-best R14 ordering.
// mode bits: 1 = GELU, 2 = write fp32 C, 4 = write fp16 plane (Ch).
// ---------------------------------------------------------------------------
struct TileP {
    const __half *Ah, *Wh;
    const float* bias;
    float* Cf;
    void *Ch;
    int lda, ldc, ldh, mode;
    float scale;
};
struct TileArr16 { TileP t[16]; };

constexpr int SM_AH = 0;          // 128 rows * 80B = 10240
constexpr int SM_BH = 10240;      // 128 rows * 80B = 10240
constexpr int SM_STAGE = 20480;
constexpr int GEMM_SMEM = 4 * SM_STAGE;   // 81920 -> 2 CTAs/SM

__global__ void __launch_bounds__(256)
gemm_tiles(TileArr16 ta, int K) {
    const TileP tp = ta.t[blockIdx.x];

    extern __shared__ char smem[];
    const uint32_t sb = smem_u32(smem);

    const int tid    = threadIdx.x;
    const int lane   = tid & 31;
    const int wid    = tid >> 5;
    const int warp_m = wid >> 2;        // 0..1
    const int warp_n = wid & 3;         // 0..3
    const int bm     = blockIdx.y * 128;

    // staging: A (2 threads/row, 32B each = 2 CP16), B same
    const int arow = tid >> 1;                       // 0..127
    const int acb  = (tid & 1) * 32;                 // byte chunk in 64B row
    const __half* gA = tp.Ah + (size_t)(bm + arow) * tp.lda + acb / 2;
    const uint32_t sA = (uint32_t)(arow * 80 + acb);

    const __half* gB = tp.Wh + (size_t)arow * K + acb / 2;
    const uint32_t sB = sA;

    const uint32_t aBase = (uint32_t)((warp_m * 64 + (lane & 15)) * 80 +
                                      ((lane >> 4) << 4));
    const uint32_t bBase = (uint32_t)((warp_n * 32 + (lane & 7) +
                                       ((lane & 16) >> 1)) * 80 +
                                      (((lane >> 3) & 1) << 4));

    float d[4][4][4];
    #pragma unroll
    for (int i = 0; i < 4; ++i)
        #pragma unroll
        for (int j = 0; j < 4; ++j)
            #pragma unroll
            for (int k = 0; k < 4; ++k) d[i][j][k] = 0.0f;

    auto load_stage = [&](int s, int kt) {
        const uint32_t sbase = sb + s * SM_STAGE;
        const int ge = kt * 32;        // element offset
        CP16(sbase + SM_AH + sA,      gA + ge);
        CP16(sbase + SM_AH + sA + 16, gA + ge + 8);
        CP16(sbase + SM_BH + sB,      gB + ge);
        CP16(sbase + SM_BH + sB + 16, gB + ge + 8);
    };

    const int KT = K >> 5;   // >= 16 always
    load_stage(0, 0); CP_COMMIT();
    load_stage(1, 1); CP_COMMIT();
    load_stage(2, 2); CP_COMMIT();

    for (int kt = 0; kt < KT; ++kt) {
        CP_WAIT2();          // stage kt landed (<=2 groups outstanding)
        __syncthreads();     // all warps done with stage kt-1 (overwrite target)

        if (kt + 3 < KT) load_stage((kt + 3) & 3, kt + 3);
        CP_COMMIT();

        const uint32_t stage = sb + (kt & 3) * SM_STAGE;
        #pragma unroll
        for (int k16 = 0; k16 < 2; ++k16) {
            uint32_t bh[4][2];
            #pragma unroll
            for (int np = 0; np < 2; ++np) {
                uint32_t addr = stage + bBase + np * (16 * 80) + k16 * 32;
                LDSM4(bh[2*np][0], bh[2*np][1], bh[2*np+1][0], bh[2*np+1][1],
                      addr + SM_BH);
            }
            // warp tile is 64 rows: mt covers 4 x 16 rows within warp_m*64
            #pragma unroll
            for (int mt = 0; mt < 4; ++mt) {
                uint32_t ah[4];
                uint32_t addr = stage + aBase + mt * (16 * 80) + k16 * 32;
                LDSM4(ah[0], ah[1], ah[2], ah[3], addr + SM_AH);
                #pragma unroll
                for (int nt = 0; nt < 4; ++nt)
                    MMA_F16(d[mt][nt], ah, bh[nt]);
            }
        }
    }

    // ------------------------- epilogue -------------------------
    const int grp  = lane >> 2;
    const int qd   = lane & 3;
    const int mode = tp.mode;
    const float sc = tp.scale;
    #pragma unroll
    for (int mt = 0; mt < 4; ++mt) {
        const int r0 = bm + warp_m * 64 + mt * 16 + grp;
        const int r1 = r0 + 8;
        #pragma unroll
        for (int nt = 0; nt < 4; ++nt) {
            const int col = warp_n * 32 + nt * 8 + qd * 2;
            float2 bb = *(const float2*)&tp.bias[col];
            float v00 = d[mt][nt][0] + bb.x;
            float v01 = d[mt][nt][1] + bb.y;
            float v10 = d[mt][nt][2] + bb.x;
            float v11 = d[mt][nt][3] + bb.y;
            if (mode & 1) {
                v00 = gelu_exact(v00); v01 = gelu_exact(v01);
                v10 = gelu_exact(v10); v11 = gelu_exact(v11);
            }
            v00 *= sc; v01 *= sc; v10 *= sc; v11 *= sc;
            if (mode & 2) {
                *(float2*)&tp.Cf[(size_t)r0 * tp.ldc + col] = make_float2(v00, v01);
                *(float2*)&tp.Cf[(size_t)r1 * tp.ldc + col] = make_float2(v10, v11);
            }
            if (mode & 4) {
                __half* Chp = (__half*)tp.Ch;
                *(uint32_t*)&Chp[(size_t)r0 * tp.ldh + col] = pack_f16(v00, v01);
                *(uint32_t*)&Chp[(size_t)r1 * tp.ldh + col] = pack_f16(v10, v11);
            }
        }
    }
}

// ---------------------------------------------------------------------------
// Rope-only builder for Q/K columns [384, 512). Q/K single fp16.
// ---------------------------------------------------------------------------
__global__ void rope_planes(const float* __restrict__ qr,
                            __half* __restrict__ qp, __half* __restrict__ kp) {
    int idx = blockIdx.x * blockDim.x + threadIdx.x;   // M*64
    if (idx >= M * 64) return;
    int m  = idx >> 6;
    int jp = (idx & 63) * 2;
    int s  = m & (S - 1);

    float vq[2], vk[2];
    #pragma unroll
    for (int e = 0; e < 2; ++e) {
        int jj = jp + e;
        int i  = jj & 63;
        float invf = expf(-(float)i * (9.2103403719761836f / 64.0f));
        float ang  = (float)s * invf;
        float sv, cv; sincosf(ang, &sv, &cv);
        float xq = qr[m * 256 + jj];
        float xk = qr[m * 256 + 128 + jj];
        float rq, rk;
        if (jj < 64) { rq = -qr[m * 256 + jj + 64]; rk = -qr[m * 256 + 128 + jj + 64]; }
        else         { rq =  qr[m * 256 + jj - 64]; rk =  qr[m * 256 + 128 + jj - 64]; }
        vq[e] = gelu_exact(xq * cv + rq * sv) * 0.125f;
        vk[e] = gelu_exact(xk * cv + rk * sv);
    }
    size_t o = (size_t)m * DC + DCC + jp;
    *(uint32_t*)&qp[o] = pack_f16(vq[0], vq[1]);
    *(uint32_t*)&kp[o] = pack_f16(vk[0], vk[1]);
}

// ---------------------------------------------------------------------------
// Flash attention via mma.sync, single fp16 Q/K/P/V, fp32 accum/softmax.
// 2-stage KV pipeline, 55.3 KB smem. qt reversed for load balance.
// ---------------------------------------------------------------------------
constexpr int AT_Q    = 0;                 // 128 rows * 144B = 18432
constexpr int AT_ST0  = 18432;
constexpr int AT_K    = 0;                 // within stage: 64 rows * 144B = 9216
constexpr int AT_V    = 9216;
constexpr int AT_STSZ = 18432;
constexpr int ATTN_SMEM = AT_ST0 + 2 * AT_STSZ;   // 55296

__global__ void __launch_bounds__(256)
attn_mma(const __half* __restrict__ Qp, const __half* __restrict__ Kp,
         const __half* __restrict__ Vp, __half* __restrict__ O) {
    extern __shared__ char smem[];
    const uint32_t sb = smem_u32(smem);

    const int qt = gridDim.x - 1 - blockIdx.x;   // heavy tiles first
    const int h = blockIdx.y, b = blockIdx.z;
    const int q0 = qt * 128;
    const int tid  = threadIdx.x;
    const int lane = tid & 31;
    const int wid  = tid >> 5;
    const int m0   = wid * 16;
    const int grp  = lane >> 2;
    const int qd   = lane & 3;
    const int bS   = b * S;
    const size_t hoff = (size_t)h * HD;

    auto load_kv = [&](int kt, int buf) {
        const uint32_t stage = sb + AT_ST0 + buf * AT_STSZ;
        int r  = tid >> 2;
        int ch = (tid & 3) * 2;
        size_t g = (size_t)(bS + kt * 64 + r) * DC + hoff + ch * 8;
        uint32_t sdst = stage + r * 144 + ch * 16;
        #pragma unroll
        for (int c = 0; c < 2; ++c) {
            CP16(sdst + AT_K + c * 16, Kp + g + c * 8);
            CP16(sdst + AT_V + c * 16, Vp + g + c * 8);
        }
    };

    {
        int r  = tid >> 1;
        int ch = (tid & 1) * 4;
        size_t g = (size_t)(bS + q0 + r) * DC + hoff + ch * 8;
        uint32_t sdst = sb + AT_Q + r * 144 + ch * 16;
        #pragma unroll
        for (int c = 0; c < 4; ++c)
            CP16(sdst + c * 16, Qp + g + c * 8);
    }
    load_kv(0, 0);
    CP_COMMIT();

    float mrow[2] = {-1e30f, -1e30f};
    float lrow[2] = {0.0f, 0.0f};
    float acc[8][4];
    #pragma unroll
    for (int j = 0; j < 8; ++j)
        #pragma unroll
        for (int c = 0; c < 4; ++c) acc[j][c] = 0.0f;

    const uint32_t aBase = sb + AT_Q + (m0 + (lane & 15)) * 144 +
                           ((lane >> 4) << 4);
    const uint32_t bRow  = ((lane & 7) + ((lane & 16) >> 1)) * 144 +
                           (((lane >> 3) & 1) << 4);
    const uint32_t vRow  = (lane & 15) * 144 + ((lane >> 4) << 4);

    const int kt_end = 2 * qt + 1;
    for (int kt = 0; kt <= kt_end; ++kt) {
        CP_WAIT0();
        __syncthreads();
        if (kt < kt_end) { load_kv(kt + 1, (kt + 1) & 1); }
        CP_COMMIT();

        const uint32_t stage = sb + AT_ST0 + (kt & 1) * AT_STSZ;
        const int k0 = kt * 64;

        float s[8][4];
        #pragma unroll
        for (int j = 0; j < 8; ++j)
            #pragma unroll
            for (int c = 0; c < 4; ++c) s[j][c] = 0.0f;

        #pragma unroll
        for (int k16 = 0; k16 < 4; ++k16) {
            uint32_t qh[4];
            LDSM4(qh[0], qh[1], qh[2], qh[3], aBase + k16 * 32);
            #pragma unroll
            for (int np = 0; np < 4; ++np) {
                uint32_t kk[4];
                uint32_t baddr = stage + bRow + np * (16 * 144) + k16 * 32;
                LDSM4(kk[0], kk[1], kk[2], kk[3], baddr + AT_K);
                MMA_F16(s[2*np],   qh, kk);
                MMA_F16(s[2*np+1], qh, kk + 2);
            }
        }

        const int row0 = q0 + m0 + grp;
        if (k0 + 63 > q0 + m0) {
            #pragma unroll
            for (int j = 0; j < 8; ++j) {
                int kg = k0 + j * 8 + qd * 2;
                if (kg     > row0)     s[j][0] = -1e30f;
                if (kg + 1 > row0)     s[j][1] = -1e30f;
                if (kg     > row0 + 8) s[j][2] = -1e30f;
                if (kg + 1 > row0 + 8) s[j][3] = -1e30f;
            }
        }

        float mx0 = -1e30f, mx1 = -1e30f;
        #pragma unroll
        for (int j = 0; j < 8; ++j) {
            mx0 = fmaxf(mx0, fmaxf(s[j][0], s[j][1]));
            mx1 = fmaxf(mx1, fmaxf(s[j][2], s[j][3]));
        }
        mx0 = fmaxf(mx0, __shfl_xor_sync(0xFFFFFFFF, mx0, 1));
        mx0 = fmaxf(mx0, __shfl_xor_sync(0xFFFFFFFF, mx0, 2));
        mx1 = fmaxf(mx1, __shfl_xor_sync(0xFFFFFFFF, mx1, 1));
        mx1 = fmaxf(mx1, __shfl_xor_sync(0xFFFFFFFF, mx1, 2));
        float mn0 = fmaxf(mrow[0], mx0);
        float mn1 = fmaxf(mrow[1], mx1);
        float al0 = fast_exp(mrow[0] - mn0);
        float al1 = fast_exp(mrow[1] - mn1);
        mrow[0] = mn0; mrow[1] = mn1;

        float sum0 = 0.0f, sum1 = 0.0f;
        #pragma unroll
        for (int j = 0; j < 8; ++j) {
            s[j][0] = fast_exp(s[j][0] - mn0); sum0 += s[j][0];
            s[j][1] = fast_exp(s[j][1] - mn0); sum0 += s[j][1];
            s[j][2] = fast_exp(s[j][2] - mn1); sum1 += s[j][2];
            s[j][3] = fast_exp(s[j][3] - mn1); sum1 += s[j][3];
        }
        sum0 += __shfl_xor_sync(0xFFFFFFFF, sum0, 1);
        sum0 += __shfl_xor_sync(0xFFFFFFFF, sum0, 2);
        sum1 += __shfl_xor_sync(0xFFFFFFFF, sum1, 1);
        sum1 += __shfl_xor_sync(0xFFFFFFFF, sum1, 2);
        lrow[0] = lrow[0] * al0 + sum0;
        lrow[1] = lrow[1] * al1 + sum1;

        #pragma unroll
        for (int j = 0; j < 8; ++j) {
            acc[j][0] *= al0; acc[j][1] *= al0;
            acc[j][2] *= al1; acc[j][3] *= al1;
        }

        #pragma unroll
        for (int k2 = 0; k2 < 4; ++k2) {
            uint32_t pa[4];
            pa[0] = pack_f16(s[2*k2][0],   s[2*k2][1]);
            pa[1] = pack_f16(s[2*k2][2],   s[2*k2][3]);
            pa[2] = pack_f16(s[2*k2+1][0], s[2*k2+1][1]);
            pa[3] = pack_f16(s[2*k2+1][2], s[2*k2+1][3]);
            #pragma unroll
            for (int np = 0; np < 4; ++np) {
                uint32_t vv[4];
                uint32_t vaddr = stage + vRow + k2 * (16 * 144) + np * 32;
                LDSM4T(vv[0], vv[1], vv[2], vv[3], vaddr + AT_V);
                MMA_F16(acc[2*np],   pa, vv);
                MMA_F16(acc[2*np+1], pa, vv + 2);
            }
        }
    }

    const float inv0 = 1.0f / lrow[0];
    const float inv1 = 1.0f / lrow[1];
    const int row0 = q0 + m0 + grp;
    const size_t ob0 = (size_t)(bS + row0) * DC + hoff;
    const size_t ob1 = (size_t)(bS + row0 + 8) * DC + hoff;
    #pragma unroll
    for (int j = 0; j < 8; ++j) {
        int col = j * 8 + qd * 2;
        *(uint32_t*)&O[ob0 + col] = pack_f16(acc[j][0] * inv0, acc[j][1] * inv0);
        *(uint32_t*)&O[ob1 + col] = pack_f16(acc[j][2] * inv1, acc[j][3] * inv1);
    }
}

// ---------------------------------------------------------------------------
// Launch
// ---------------------------------------------------------------------------
extern "C" void kernel_launch(void* const* d_in, const int* in_sizes, int n_in,
                              void* d_out, int out_size) {
    const float* x     = (const float*)d_in[0];
    const float* CQ_w  = (const float*)d_in[1];
    const float* CQ_b  = (const float*)d_in[2];
    const float* CQC_w = (const float*)d_in[3];
    const float* CQC_b = (const float*)d_in[4];
    const float* CQR_w = (const float*)d_in[5];
    const float* CQR_b = (const float*)d_in[6];
    const float* CKV_w = (const float*)d_in[7];
    const float* CKV_b = (const float*)d_in[8];
    const float* CKR_w = (const float*)d_in[9];
    const float* CKR_b = (const float*)d_in[10];
    const float* CKC_w = (const float*)d_in[11];
    const float* CKC_b = (const float*)d_in[12];
    const float* CV_w  = (const float*)d_in[13];
    const float* CV_b  = (const float*)d_in[14];
    const float* OUT_w = (const float*)d_in[15];
    const float* OUT_b = (const float*)d_in[16];
    float* out = (float*)d_out;

    __half *xp, *wh, *cqkv, *qp, *kp, *vp, *op;
    float *qr;
    cudaGetSymbolAddress((void**)&xp,   g_x);
    cudaGetSymbolAddress((void**)&wh,   g_wh);
    cudaGetSymbolAddress((void**)&cqkv, g_cqkv);
    cudaGetSymbolAddress((void**)&qp,   g_q);
    cudaGetSymbolAddress((void**)&kp,   g_k);
    cudaGetSymbolAddress((void**)&vp,   g_v);
    cudaGetSymbolAddress((void**)&op,   g_o);
    cudaGetSymbolAddress((void**)&qr,   g_qr);

    cudaFuncSetAttribute(gemm_tiles,
                         cudaFuncAttributeMaxDynamicSharedMemorySize, GEMM_SMEM);
    cudaFuncSetAttribute(attn_mma,
                         cudaFuncAttributeMaxDynamicSharedMemorySize, ATTN_SMEM);

    cvt_x<<<(M * 2048 / 4 + 255) / 256, 256>>>(x, xp, M * 2048 / 4);
    cvt_weights<<<((int)QB7 + 255) / 256, 256>>>(CQ_w, CKV_w, CQR_w, CKR_w,
                                                 CQC_w, CKC_w, CV_w, OUT_w, wh);

    dim3 blk(256);
    const int GY = M / 128;   // 64 row tiles of 128

    auto mkTile = [](const __half* Ah, int lda, const __half* Wh,
                     const float* bias, float* Cf, int ldc,
                     void* Ch, int ldh, int mode, float scale) {
        TileP t;
        t.Ah = Ah; t.Wh = Wh; t.bias = bias;
        t.Cf = Cf; t.Ch = Ch;
        t.lda = lda; t.ldc = ldc; t.ldh = ldh; t.mode = mode; t.scale = scale;
        return t;
    };

    // launch A: CQ | CKV | CQR | CKR  (K = 2048, 10 column tiles)
    {
        TileArr16 ta;
        for (int t = 0; t < 4; ++t)   // cq -> fp16, cqkv cols [0,512)
            ta.t[t] = mkTile(xp, 2048, wh + OFF_Q + (size_t)t*128*2048,
                             CQ_b + t*128, nullptr, 0,
                             cqkv + t*128, 1024, 1|4, 1.0f);
        for (int t = 0; t < 4; ++t)   // ckv -> fp16, cqkv cols [512,1024)
            ta.t[4+t] = mkTile(xp, 2048, wh + OFF_KV + (size_t)t*128*2048,
                             CKV_b + t*128, nullptr, 0,
                             cqkv + 512 + t*128, 1024, 1|4, 1.0f);
        ta.t[8] = mkTile(xp, 2048, wh + OFF_QR,
                         CQR_b, qr, 256, nullptr, 0, 2, 1.0f);
        ta.t[9] = mkTile(xp, 2048, wh + OFF_KR,
                         CKR_b, qr + 128, 256, nullptr, 0, 2, 1.0f);
        gemm_tiles<<<dim3(10, GY), blk, GEMM_SMEM>>>(ta, 2048);
    }

    // launch B: CQC | CKC | CV  (K = 512, 10 column tiles)
    {
        TileArr16 ta;
        for (int t = 0; t < 3; ++t)   // cqc -> Q fp16, gelu*0.125
            ta.t[t] = mkTile(cqkv, 1024, wh + OFF_QC + (size_t)t*128*512,
                             CQC_b + t*128, nullptr, 0,
                             qp + t*128, 512, 1|4, 0.125f);
        for (int t = 0; t < 3; ++t)   // ckc -> K fp16, gelu
            ta.t[3+t] = mkTile(cqkv + 512, 1024, wh + OFF_KC + (size_t)t*128*512,
                             CKC_b + t*128, nullptr, 0,
                             kp + t*128, 512, 1|4, 1.0f);
        for (int t = 0; t < 4; ++t)   // V -> fp16 (no gelu)
            ta.t[6+t] = mkTile(cqkv + 512, 1024, wh + OFF_V + (size_t)t*128*512,
                             CV_b + t*128, nullptr, 0,
                             vp + t*128, 512, 4, 1.0f);
        gemm_tiles<<<dim3(10, GY), blk, GEMM_SMEM>>>(ta, 512);
    }

    // rope columns [384,512) of Q/K
    rope_planes<<<(M * 64 + 255) / 256, 256>>>(qr, qp, kp);

    // causal flash attention -> fp16 O
    attn_mma<<<dim3(S/128, H, B), dim3(256), ATTN_SMEM>>>(qp, kp, vp, op);

    // launch C: OUT  (K = 512, 16 column tiles)
    {
        TileArr16 ta;
        for (int t = 0; t < 16; ++t)
            ta.t[t] = mkTile(op, 512, wh + OFF_OUT + (size_t)t*128*512,
                             OUT_b + t*128, out + t*128, 2048,
                             nullptr, 0, 2, 1.0f);
        gemm_tiles<<<dim3(16, GY), blk, GEMM_SMEM>>>(ta, 512);
    }
}